// round 13
// baseline (speedup 1.0000x reference)
#include <cuda_runtime.h>
#include <cuda_fp16.h>
#include <cstdint>

// ---------------- problem constants ----------------
#define NB     8
#define C_     768
#define NHEAD  12
#define M_TOT  32768
#define HID    3072
#define ADA6   (6*C_)
#define REGSZ  ((size_t)M_TOT * C_)
#define KC     64

// ---------------- scratch (device globals) ----------------
__device__ float g_ada[NB*ADA6];
__device__ __half g_qkv[(size_t)3*M_TOT*C_];
__device__ float g_xnew[(size_t)M_TOT*C_];
__device__ __half g_actA[(size_t)M_TOT*C_];
__device__ __half g_actB[(size_t)M_TOT*HID];
__device__ __half g_wqkv[3*C_*C_];
__device__ __half g_wproj[C_*C_];
__device__ __half g_wfc1[HID*C_];
__device__ __half g_wfc2[C_*HID];

// ---------------- ptx helpers ----------------
__device__ __forceinline__ uint32_t smem_u32(const void* p) {
    uint32_t a;
    asm("{ .reg .u64 t; cvta.to.shared.u64 t, %1; cvt.u32.u64 %0, t; }" : "=r"(a) : "l"(p));
    return a;
}
__device__ __forceinline__ void cp16(uint32_t dst, const void* src) {
    asm volatile("cp.async.cg.shared.global [%0], [%1], 16;" :: "r"(dst), "l"(src));
}
__device__ __forceinline__ void cp_commit() { asm volatile("cp.async.commit_group;" ::: "memory"); }
template<int N> __device__ __forceinline__ void cp_wait() {
    asm volatile("cp.async.wait_group %0;" :: "n"(N) : "memory");
}
__device__ __forceinline__ void ldsm4(uint32_t& r0, uint32_t& r1, uint32_t& r2, uint32_t& r3,
                                      uint32_t addr) {
    asm volatile("ldmatrix.sync.aligned.m8n8.x4.shared.b16 {%0,%1,%2,%3}, [%4];"
                 : "=r"(r0), "=r"(r1), "=r"(r2), "=r"(r3) : "r"(addr));
}
__device__ __forceinline__ void ldsm4t(uint32_t& r0, uint32_t& r1, uint32_t& r2, uint32_t& r3,
                                       uint32_t addr) {
    asm volatile("ldmatrix.sync.aligned.m8n8.x4.trans.shared.b16 {%0,%1,%2,%3}, [%4];"
                 : "=r"(r0), "=r"(r1), "=r"(r2), "=r"(r3) : "r"(addr));
}
// fp16 inputs, fp32 accumulate
__device__ __forceinline__ void mma_hf(float* c, const uint32_t* a,
                                       uint32_t b0, uint32_t b1) {
    asm volatile(
        "mma.sync.aligned.m16n8k16.row.col.f32.f16.f16.f32 "
        "{%0,%1,%2,%3}, {%4,%5,%6,%7}, {%8,%9}, {%0,%1,%2,%3};"
        : "+f"(c[0]), "+f"(c[1]), "+f"(c[2]), "+f"(c[3])
        : "r"(a[0]), "r"(a[1]), "r"(a[2]), "r"(a[3]), "r"(b0), "r"(b1));
}
__device__ __forceinline__ uint32_t swz(uint32_t o) { return o ^ ((o >> 3) & 0x70); }
__device__ __forceinline__ uint32_t packh(float x, float y) {
    __half2 h = __floats2half2_rn(x, y);
    return *(uint32_t*)&h;
}
__device__ __forceinline__ float tanha(float x) {
    float y;
    asm("tanh.approx.f32 %0, %1;" : "=f"(y) : "f"(x));
    return y;
}

// ---------------- ada: silu(c) @ ada_w^T + ada_b ----------------
__global__ void ada_kernel(const float* __restrict__ c_in,
                           const float* __restrict__ ada_w,
                           const float* __restrict__ ada_b) {
    const int warp = threadIdx.x >> 5, lane = threadIdx.x & 31;
    const int j = blockIdx.x * 4 + warp;
    const int n = blockIdx.y;
    const float* wrow = ada_w + (size_t)j * C_;
    const float* crow = c_in + n * C_;
    float s = 0.f;
    for (int k = lane; k < C_; k += 32) {
        float cv = crow[k];
        s += (cv / (1.f + __expf(-cv))) * wrow[k];
    }
    #pragma unroll
    for (int o = 16; o > 0; o >>= 1) s += __shfl_xor_sync(0xffffffffu, s, o);
    if (lane == 0) g_ada[n*ADA6 + j] = s + ada_b[j];
}

// ---------------- merged weight conversion fp32 -> fp16 ----------------
#define NW0 (3*C_*C_)
#define NW1 (C_*C_)
#define NW2 (HID*C_)
#define NW3 (C_*HID)
#define NWTOT (NW0+NW1+NW2+NW3)
__global__ void f2h_all(const float* __restrict__ s0, const float* __restrict__ s1,
                        const float* __restrict__ s2, const float* __restrict__ s3) {
    int i = (blockIdx.x * blockDim.x + threadIdx.x) * 4;
    const float* s;
    __half* d;
    int off;
    if (i < NW0)                 { s = s0; d = g_wqkv;  off = i; }
    else if (i < NW0+NW1)        { s = s1; d = g_wproj; off = i - NW0; }
    else if (i < NW0+NW1+NW2)    { s = s2; d = g_wfc1;  off = i - NW0 - NW1; }
    else if (i < NWTOT)          { s = s3; d = g_wfc2;  off = i - NW0 - NW1 - NW2; }
    else return;
    float4 v = *(const float4*)(s + off);
    ((__half2*)(d + off))[0] = __floats2half2_rn(v.x, v.y);
    ((__half2*)(d + off))[1] = __floats2half2_rn(v.z, v.w);
}

// ---------------- LayerNorm + adaLN modulation -> fp16 ----------------
template<int SEQ>
__global__ void __launch_bounds__(192) ln_mod_kernel(const float* __restrict__ xin) {
    const int t = blockIdx.x;
    const int tid = threadIdx.x;
    const int wid = tid >> 5, lane = tid & 31;
    int n;
    const float* xr;
    if (SEQ) {
        n = t >> 12;
        xr = g_xnew + (size_t)t * C_;
    } else {
        const int win = t >> 6, tw = t & 63;
        n = win >> 6;
        const int wi = win & 63;
        const int gi = ((wi >> 3) << 3) + (tw >> 3);
        const int gj = ((wi & 7) << 3) + (tw & 7);
        const int i0 = (gi + 4) & 63, j0 = (gj + 4) & 63;
        xr = xin + (((size_t)n << 12) + (i0 << 6) + j0) * C_;
    }
    const int cix = tid * 4;
    float4 v = *(const float4*)(xr + cix);
    float s  = v.x + v.y + v.z + v.w;
    float ss = v.x*v.x + v.y*v.y + v.z*v.z + v.w*v.w;
    __shared__ float red[14];
    #pragma unroll
    for (int o = 16; o > 0; o >>= 1) {
        s  += __shfl_xor_sync(0xffffffffu, s,  o);
        ss += __shfl_xor_sync(0xffffffffu, ss, o);
    }
    if (lane == 0) { red[wid] = s; red[6 + wid] = ss; }
    __syncthreads();
    if (tid == 0) {
        float a = 0.f, b = 0.f;
        #pragma unroll
        for (int w = 0; w < 6; w++) { a += red[w]; b += red[6 + w]; }
        const float mean = a * (1.f / 768.f);
        const float var  = b * (1.f / 768.f) - mean * mean;
        red[12] = mean;
        red[13] = rsqrtf(var + 1e-6f);
    }
    __syncthreads();
    const float mean = red[12], rstd = red[13];
    const float4 sc = *(const float4*)(g_ada + n*ADA6 + (SEQ ? 4 : 1) * C_ + cix);
    const float4 sh = *(const float4*)(g_ada + n*ADA6 + (SEQ ? 3 : 0) * C_ + cix);
    uint2 o;
    o.x = packh((v.x - mean) * rstd * (1.f + sc.x) + sh.x,
                (v.y - mean) * rstd * (1.f + sc.y) + sh.y);
    o.y = packh((v.z - mean) * rstd * (1.f + sc.z) + sh.z,
                (v.w - mean) * rstd * (1.f + sc.w) + sh.w);
    *(uint2*)(g_actA + (size_t)t * C_ + cix) = o;
}

// ---------------- HMMA fp16 GEMM (fp32 acc): C[m,n] = sum_k A[m,k]*W[n,k] ----------------
// BM=128. BN=256 (MODE 0,2; warp tile 64x64) or BN=128 (MODE 1,3; warp tile 64x32,
// R4-proven rate, grid 1536 CTAs -> wave util 94.3% vs 86.5%).
#define BM 128

template<int MODE>
struct GemmCfg {
    static constexpr int BN   = (MODE == 1 || MODE == 3) ? 128 : 256;
    static constexpr int K    = (MODE == 3) ? HID : C_;
    static constexpr int BUFB = (BM + BN) * 128;
    static constexpr int SMEM = 4 * BUFB;
};

template<int MODE>
__global__ void __launch_bounds__(256, 1) gemm_tc(
    const float* __restrict__ bias,
    const float* __restrict__ x_seq,
    float* __restrict__ dout)
{
    constexpr int BN   = GemmCfg<MODE>::BN;
    constexpr int K    = GemmCfg<MODE>::K;
    constexpr int NCH  = K / KC;
    constexpr int BUFB = GemmCfg<MODE>::BUFB;
    constexpr int WN   = BN / 4;            // 64 or 32
    constexpr int NJ   = WN / 16;           // 4 or 2
    const __half* A = (MODE == 3) ? g_actB : g_actA;
    const __half* W = (MODE == 0) ? g_wqkv : (MODE == 1) ? g_wproj
                    : (MODE == 2) ? g_wfc1 : g_wfc2;

    extern __shared__ char smem[];
    const uint32_t s0 = smem_u32(smem);
    const int tid = threadIdx.x;
    const int wid = tid >> 5, lane = tid & 31;
    const int bm = blockIdx.y * BM, bn = blockIdx.x * BN;

    // producer mapping:
    //  BN=256: all threads load B row tid;            threads <128 load A row tid
    //  BN=128: threads >=128 load B row tid-128;      threads <128 load A row tid
    const int brow = (BN == 256) ? tid : (tid & 127);
    const __half* Brow = W + (size_t)(bn + brow) * K;
    const __half* Arow = A + (size_t)(bm + (tid & 127)) * K;
    uint32_t bofs[8], aofs[8];
    #pragma unroll
    for (int s = 0; s < 8; s++) {
        bofs[s] = (uint32_t)(BM * 128) + swz((uint32_t)brow * 128 + s * 16);
        aofs[s] = swz((uint32_t)(tid & 127) * 128 + s * 16);
    }
    auto load_chunk = [&](int i) {
        const uint32_t buf = s0 + (uint32_t)(i & 3) * BUFB;
        if (BN == 256 || tid >= 128) {
            const __half* bsrc = Brow + i * KC;
            #pragma unroll
            for (int s = 0; s < 8; s++) cp16(buf + bofs[s], bsrc + s * 8);
        }
        if (tid < 128) {
            const __half* asrc = Arow + i * KC;
            #pragma unroll
            for (int s = 0; s < 8; s++) cp16(buf + aofs[s], asrc + s * 8);
        }
        cp_commit();
    };
    load_chunk(0); load_chunk(1); load_chunk(2);

    const int wm = wid >> 2, wn = wid & 3;
    uint32_t aOff[4], aXor[4];
    #pragma unroll
    for (int mi = 0; mi < 4; mi++) {
        const int r = wm * 64 + mi * 16 + (lane & 15);
        aOff[mi] = (uint32_t)r * 128 + ((lane >> 4) << 4);
        aXor[mi] = ((uint32_t)(r & 7)) << 4;
    }
    uint32_t bOff[NJ], bXor[NJ];
    #pragma unroll
    for (int nj = 0; nj < NJ; nj++) {
        const int r = wn * WN + nj * 16 + (lane & 15);
        bOff[nj] = (uint32_t)(BM * 128) + (uint32_t)r * 128 + ((lane >> 4) << 4);
        bXor[nj] = ((uint32_t)(r & 7)) << 4;
    }

    uint32_t aR[2][4][4], bR[2][NJ][4];
    auto do_ldsm = [&](uint32_t buf, int ks, int p) {
        const uint32_t kb = (uint32_t)ks * 32;
        #pragma unroll
        for (int mi = 0; mi < 4; mi++)
            ldsm4(aR[p][mi][0], aR[p][mi][1], aR[p][mi][2], aR[p][mi][3],
                  buf + (aOff[mi] & ~0x70u) + (((aOff[mi] & 0x70u) + kb) ^ aXor[mi]));
        #pragma unroll
        for (int nj = 0; nj < NJ; nj++)
            ldsm4(bR[p][nj][0], bR[p][nj][1], bR[p][nj][2], bR[p][nj][3],
                  buf + (bOff[nj] & ~0x70u) + (((bOff[nj] & 0x70u) + kb) ^ bXor[nj]));
    };

    float acc[4][2*NJ][4];
    #pragma unroll
    for (int mi = 0; mi < 4; mi++)
        #pragma unroll
        for (int ni = 0; ni < 2*NJ; ni++)
            #pragma unroll
            for (int e = 0; e < 4; e++) acc[mi][ni][e] = 0.f;

    cp_wait<2>();
    __syncthreads();
    do_ldsm(s0, 0, 0);

    for (int i = 0; i < NCH; i++) {
        const uint32_t buf = s0 + (uint32_t)(i & 3) * BUFB;
        #pragma unroll
        for (int ks = 0; ks < 4; ks++) {
            const int p = ks & 1;
            if (ks < 3) {
                do_ldsm(buf, ks + 1, p ^ 1);
            } else if (i + 1 < NCH) {
                if (i + 2 < NCH) cp_wait<1>(); else cp_wait<0>();
                __syncthreads();
                if (i + 3 < NCH) load_chunk(i + 3);
                do_ldsm(s0 + (uint32_t)((i + 1) & 3) * BUFB, 0, p ^ 1);
            }
            #pragma unroll
            for (int mi = 0; mi < 4; mi++) {
                #pragma unroll
                for (int nj = 0; nj < NJ; nj++) {
                    mma_hf(acc[mi][nj*2+0], aR[p][mi], bR[p][nj][0], bR[p][nj][2]);
                    mma_hf(acc[mi][nj*2+1], aR[p][mi], bR[p][nj][1], bR[p][nj][3]);
                }
            }
        }
    }

    // ---------------- epilogue ----------------
    const int rIn = lane >> 2;
    const int cIn = (lane & 3) * 2;
    #pragma unroll
    for (int mi = 0; mi < 4; mi++) {
        #pragma unroll
        for (int h = 0; h < 2; h++) {
            const int row = bm + wm * 64 + mi * 16 + rIn + h * 8;
            if constexpr (MODE == 0) {
                const int win = row >> 6, tw = row & 63;
                #pragma unroll
                for (int ni = 0; ni < 2*NJ; ni++) {
                    const int g = bn + wn * WN + ni * 8 + cIn;
                    const int which = g / 768;
                    const int head = (g >> 6) % 12;
                    const int d0 = g & 63;
                    __half* dst = g_qkv + (size_t)which * REGSZ
                               + (((size_t)(win * NHEAD + head)) << 12) + (tw << 6) + d0;
                    *(__half2*)dst = __floats2half2_rn(
                        acc[mi][ni][h*2+0] + __ldg(bias + g),
                        acc[mi][ni][h*2+1] + __ldg(bias + g + 1));
                }
            } else if constexpr (MODE == 1) {
                const int win = row >> 6, tw = row & 63;
                const int n = win >> 6, wi = win & 63;
                const int gi = ((wi >> 3) << 3) + (tw >> 3);
                const int gj = ((wi & 7) << 3) + (tw & 7);
                const int i0 = (gi + 4) & 63, j0 = (gj + 4) & 63;
                const size_t srow = ((size_t)n << 12) + (i0 << 6) + j0;
                const float* xr = x_seq + srow * C_;
                float* dst = g_xnew + srow * C_;
                const float* gp = g_ada + n * ADA6 + 2 * C_;
                #pragma unroll
                for (int ni = 0; ni < 2*NJ; ni++) {
                    const int g = bn + wn * WN + ni * 8 + cIn;
                    float2 v;
                    v.x = xr[g]   + gp[g]   * (acc[mi][ni][h*2+0] + __ldg(bias + g));
                    v.y = xr[g+1] + gp[g+1] * (acc[mi][ni][h*2+1] + __ldg(bias + g + 1));
                    *(float2*)(dst + g) = v;
                }
            } else if constexpr (MODE == 2) {
                __half* dst = g_actB + (size_t)row * HID;
                #pragma unroll
                for (int ni = 0; ni < 2*NJ; ni++) {
                    const int g = bn + wn * WN + ni * 8 + cIn;
                    float u0 = acc[mi][ni][h*2+0] + __ldg(bias + g);
                    float u1 = acc[mi][ni][h*2+1] + __ldg(bias + g + 1);
                    float t0 = tanha(0.7978845608028654f * (u0 + 0.044715f * u0 * u0 * u0));
                    float t1 = tanha(0.7978845608028654f * (u1 + 0.044715f * u1 * u1 * u1));
                    *(__half2*)(dst + g) =
                        __floats2half2_rn(0.5f * u0 * (1.f + t0), 0.5f * u1 * (1.f + t1));
                }
            } else {
                const int n = row >> 12;
                const float* xr = g_xnew + (size_t)row * C_;
                const float* gp = g_ada + n * ADA6 + 5 * C_;
                float* dst = dout + (size_t)row * C_;
                #pragma unroll
                for (int ni = 0; ni < 2*NJ; ni++) {
                    const int g = bn + wn * WN + ni * 8 + cIn;
                    float2 v;
                    v.x = xr[g]   + gp[g]   * (acc[mi][ni][h*2+0] + __ldg(bias + g));
                    v.y = xr[g+1] + gp[g+1] * (acc[mi][ni][h*2+1] + __ldg(bias + g + 1));
                    *(float2*)(dst + g) = v;
                }
            }
        }
    }
}

// ---------------- HMMA window attention: 2 heads per CTA, fp16 in, fp32 acc ----------------
__global__ void __launch_bounds__(256, 4) attn_hmma() {
    __shared__ __align__(1024) __half sm[2 * 3 * 4096];
    const uint32_t sb = smem_u32(sm);
    const int bid = blockIdx.x;
    const int win = bid / 6, hp = bid - 6 * win;
    const int tid = threadIdx.x, wid = tid >> 5, lane = tid & 31;

    {
        const int hh = tid >> 7;
        const int t0 = tid & 127;
        const __half* qb = g_qkv + (size_t)(win * NHEAD + hp * 2 + hh) * 4096;
        const uint32_t hsb = sb + (uint32_t)hh * 24576u;
        const int r = t0 & 63;
        const __half* src = ((t0 < 64) ? qb : (qb + REGSZ)) + r * 64;
        const uint32_t base = hsb + ((t0 < 64) ? 0u : 8192u);
        #pragma unroll
        for (int s = 0; s < 8; s++)
            cp16(base + swz((uint32_t)r * 128 + s * 16), src + s * 8);
        const __half* vb = qb + 2 * REGSZ;
        const int vr = t0 >> 1;
        const int c0 = (t0 & 1) * 4;
        #pragma unroll
        for (int s = 0; s < 4; s++)
            cp16(hsb + 16384u + swz((uint32_t)vr * 128 + (c0 + s) * 16),
                 vb + vr * 64 + (c0 + s) * 8);
    }
    cp_commit();
    cp_wait<0>();
    __syncthreads();

    const int hw = wid >> 2, w4 = wid & 3;
    const uint32_t hsb = sb + (uint32_t)hw * 24576u;
    const int head = hp * 2 + hw;
    const int lr = lane & 15, lc = lane >> 4;

    uint32_t aF[4][4];
    #pragma unroll
    for (int ks = 0; ks < 4; ks++)
        ldsm4(aF[ks][0], aF[ks][1], aF[ks][2], aF[ks][3],
              hsb + swz((uint32_t)(16 * w4 + lr) * 128 + lc * 16 + ks * 32));

    float S[8][4];
    #pragma unroll
    for (int f = 0; f < 8; f++)
        #pragma unroll
        for (int e = 0; e < 4; e++) S[f][e] = 0.f;

    #pragma unroll
    for (int nj = 0; nj < 4; nj++) {
        #pragma unroll
        for (int ks = 0; ks < 4; ks++) {
            uint32_t b0, b1, b2, b3;
            ldsm4(b0, b1, b2, b3,
                  hsb + 8192u + swz((uint32_t)(nj * 16 + lr) * 128 + lc * 16 + ks * 32));
            mma_hf(S[2*nj+0], aF[ks], b0, b2);
            mma_hf(S[2*nj+1], aF[ks], b1, b3);
        }
    }

    float mx0 = -1e30f, mx1 = -1e30f;
    #pragma unroll
    for (int f = 0; f < 8; f++) {
        #pragma unroll
        for (int e = 0; e < 4; e++) S[f][e] *= 0.125f;
        mx0 = fmaxf(mx0, fmaxf(S[f][0], S[f][1]));
        mx1 = fmaxf(mx1, fmaxf(S[f][2], S[f][3]));
    }
    mx0 = fmaxf(mx0, __shfl_xor_sync(0xffffffffu, mx0, 1));
    mx0 = fmaxf(mx0, __shfl_xor_sync(0xffffffffu, mx0, 2));
    mx1 = fmaxf(mx1, __shfl_xor_sync(0xffffffffu, mx1, 1));
    mx1 = fmaxf(mx1, __shfl_xor_sync(0xffffffffu, mx1, 2));
    float sm0 = 0.f, sm1 = 0.f;
    #pragma unroll
    for (int f = 0; f < 8; f++) {
        S[f][0] = __expf(S[f][0] - mx0); sm0 += S[f][0];
        S[f][1] = __expf(S[f][1] - mx0); sm0 += S[f][1];
        S[f][2] = __expf(S[f][2] - mx1); sm1 += S[f][2];
        S[f][3] = __expf(S[f][3] - mx1); sm1 += S[f][3];
    }
    sm0 += __shfl_xor_sync(0xffffffffu, sm0, 1);
    sm0 += __shfl_xor_sync(0xffffffffu, sm0, 2);
    sm1 += __shfl_xor_sync(0xffffffffu, sm1, 1);
    sm1 += __shfl_xor_sync(0xffffffffu, sm1, 2);
    const float iv0 = 1.f / sm0, iv1 = 1.f / sm1;
    #pragma unroll
    for (int f = 0; f < 8; f++) {
        S[f][0] *= iv0; S[f][1] *= iv0; S[f][2] *= iv1; S[f][3] *= iv1;
    }

    uint32_t aP[4][4];
    #pragma unroll
    for (int ks = 0; ks < 4; ks++) {
        aP[ks][0] = packh(S[2*ks+0][0], S[2*ks+0][1]);
        aP[ks][1] = packh(S[2*ks+0][2], S[2*ks+0][3]);
        aP[ks][2] = packh(S[2*ks+1][0], S[2*ks+1][1]);
        aP[ks][3] = packh(S[2*ks+1][2], S[2*ks+1][3]);
    }

    float O[8][4];
    #pragma unroll
    for (int f = 0; f < 8; f++)
        #pragma unroll
        for (int e = 0; e < 4; e++) O[f][e] = 0.f;
    #pragma unroll
    for (int ks = 0; ks < 4; ks++) {
        #pragma unroll
        for (int nj = 0; nj < 4; nj++) {
            uint32_t r0, r1, r2, r3;
            ldsm4t(r0, r1, r2, r3,
                   hsb + 16384u + swz((uint32_t)(16 * ks + lr) * 128 + (2 * nj + lc) * 16));
            mma_hf(O[2*nj+0], aP[ks], r0, r1);
            mma_hf(O[2*nj+1], aP[ks], r2, r3);
        }
    }

    const int r0row = 16 * w4 + (lane >> 2);
    const int q2 = (lane & 3) * 2;
    #pragma unroll
    for (int f = 0; f < 8; f++) {
        __half* d0 = g_actA + (size_t)(win * 64 + r0row) * C_ + head * 64 + 8 * f + q2;
        *(__half2*)d0 = __floats2half2_rn(O[f][0], O[f][1]);
        *(__half2*)(d0 + 8 * C_) = __floats2half2_rn(O[f][2], O[f][3]);
    }
}

// ---------------- launcher ----------------
extern "C" void kernel_launch(void* const* d_in, const int* in_sizes, int n_in,
                              void* d_out, int out_size) {
    const float* x_seq  = (const float*)d_in[0];
    const float* c_in   = (const float*)d_in[1];
    const float* qkv_w  = (const float*)d_in[2];
    const float* qkv_b  = (const float*)d_in[3];
    const float* proj_w = (const float*)d_in[4];
    const float* proj_b = (const float*)d_in[5];
    const float* fc1_w  = (const float*)d_in[6];
    const float* fc1_b  = (const float*)d_in[7];
    const float* fc2_w  = (const float*)d_in[8];
    const float* fc2_b  = (const float*)d_in[9];
    const float* ada_w  = (const float*)d_in[10];
    const float* ada_b  = (const float*)d_in[11];
    float* out = (float*)d_out;

    cudaFuncSetAttribute(gemm_tc<0>, cudaFuncAttributeMaxDynamicSharedMemorySize, GemmCfg<0>::SMEM);
    cudaFuncSetAttribute(gemm_tc<1>, cudaFuncAttributeMaxDynamicSharedMemorySize, GemmCfg<1>::SMEM);
    cudaFuncSetAttribute(gemm_tc<2>, cudaFuncAttributeMaxDynamicSharedMemorySize, GemmCfg<2>::SMEM);
    cudaFuncSetAttribute(gemm_tc<3>, cudaFuncAttributeMaxDynamicSharedMemorySize, GemmCfg<3>::SMEM);

    ada_kernel<<<dim3(ADA6/4, NB), 128>>>(c_in, ada_w, ada_b);                       // 1
    f2h_all<<<(NWTOT/4 + 255)/256, 256>>>(qkv_w, proj_w, fc1_w, fc2_w);              // 2
    ln_mod_kernel<0><<<M_TOT, 192>>>(x_seq);                                         // 3
    gemm_tc<0><<<dim3(9, 256), 256, GemmCfg<0>::SMEM>>>(qkv_b, nullptr, nullptr);    // 4 <- ncu
    attn_hmma<<<512*6, 256>>>();                                                     // 5
    gemm_tc<1><<<dim3(6, 256), 256, GemmCfg<1>::SMEM>>>(proj_b, x_seq, nullptr);     // 6
    ln_mod_kernel<1><<<M_TOT, 192>>>(nullptr);                                       // 7
    gemm_tc<2><<<dim3(12, 256), 256, GemmCfg<2>::SMEM>>>(fc1_b, nullptr, nullptr);   // 8
    gemm_tc<3><<<dim3(6, 256), 256, GemmCfg<3>::SMEM>>>(fc2_b, nullptr, out);        // 9
}

// round 15
// speedup vs baseline: 1.0261x; 1.0261x over previous
#include <cuda_runtime.h>
#include <cuda_fp16.h>
#include <cstdint>

// ---------------- problem constants ----------------
#define NB     8
#define C_     768
#define NHEAD  12
#define M_TOT  32768
#define HID    3072
#define ADA6   (6*C_)
#define REGSZ  ((size_t)M_TOT * C_)
#define KC     64

// ---------------- scratch (device globals) ----------------
__device__ float g_ada[NB*ADA6];
__device__ __half g_qkv[(size_t)3*M_TOT*C_];
__device__ float g_xnew[(size_t)M_TOT*C_];
__device__ __half g_actA[(size_t)M_TOT*C_];   // ln0 out / attn out (window rows)
__device__ __half g_actC[(size_t)M_TOT*C_];   // ln1 out (sequence rows)  <- NEW, no alias
__device__ __half g_actB[(size_t)M_TOT*HID];
__device__ __half g_wqkv[3*C_*C_];
__device__ __half g_wproj[C_*C_];
__device__ __half g_wfc1[HID*C_];
__device__ __half g_wfc2[C_*HID];
__device__ int g_cnt1[256];          // zero-init; self-resetting completion counters

// ---------------- ptx helpers ----------------
__device__ __forceinline__ uint32_t smem_u32(const void* p) {
    uint32_t a;
    asm("{ .reg .u64 t; cvta.to.shared.u64 t, %1; cvt.u32.u64 %0, t; }" : "=r"(a) : "l"(p));
    return a;
}
__device__ __forceinline__ void cp16(uint32_t dst, const void* src) {
    asm volatile("cp.async.cg.shared.global [%0], [%1], 16;" :: "r"(dst), "l"(src));
}
__device__ __forceinline__ void cp_commit() { asm volatile("cp.async.commit_group;" ::: "memory"); }
template<int N> __device__ __forceinline__ void cp_wait() {
    asm volatile("cp.async.wait_group %0;" :: "n"(N) : "memory");
}
__device__ __forceinline__ void ldsm4(uint32_t& r0, uint32_t& r1, uint32_t& r2, uint32_t& r3,
                                      uint32_t addr) {
    asm volatile("ldmatrix.sync.aligned.m8n8.x4.shared.b16 {%0,%1,%2,%3}, [%4];"
                 : "=r"(r0), "=r"(r1), "=r"(r2), "=r"(r3) : "r"(addr));
}
__device__ __forceinline__ void ldsm4t(uint32_t& r0, uint32_t& r1, uint32_t& r2, uint32_t& r3,
                                       uint32_t addr) {
    asm volatile("ldmatrix.sync.aligned.m8n8.x4.trans.shared.b16 {%0,%1,%2,%3}, [%4];"
                 : "=r"(r0), "=r"(r1), "=r"(r2), "=r"(r3) : "r"(addr));
}
// fp16 inputs, fp32 accumulate
__device__ __forceinline__ void mma_hf(float* c, const uint32_t* a,
                                       uint32_t b0, uint32_t b1) {
    asm volatile(
        "mma.sync.aligned.m16n8k16.row.col.f32.f16.f16.f32 "
        "{%0,%1,%2,%3}, {%4,%5,%6,%7}, {%8,%9}, {%0,%1,%2,%3};"
        : "+f"(c[0]), "+f"(c[1]), "+f"(c[2]), "+f"(c[3])
        : "r"(a[0]), "r"(a[1]), "r"(a[2]), "r"(a[3]), "r"(b0), "r"(b1));
}
__device__ __forceinline__ uint32_t swz(uint32_t o) { return o ^ ((o >> 3) & 0x70); }
__device__ __forceinline__ uint32_t packh(float x, float y) {
    __half2 h = __floats2half2_rn(x, y);
    return *(uint32_t*)&h;
}
__device__ __forceinline__ float tanha(float x) {
    float y;
    asm("tanh.approx.f32 %0, %1;" : "=f"(y) : "f"(x));
    return y;
}

// ---------------- ada: silu(c) @ ada_w^T + ada_b ----------------
__global__ void ada_kernel(const float* __restrict__ c_in,
                           const float* __restrict__ ada_w,
                           const float* __restrict__ ada_b) {
    const int warp = threadIdx.x >> 5, lane = threadIdx.x & 31;
    const int j = blockIdx.x * 4 + warp;
    const int n = blockIdx.y;
    const float* wrow = ada_w + (size_t)j * C_;
    const float* crow = c_in + n * C_;
    float s = 0.f;
    for (int k = lane; k < C_; k += 32) {
        float cv = crow[k];
        s += (cv / (1.f + __expf(-cv))) * wrow[k];
    }
    #pragma unroll
    for (int o = 16; o > 0; o >>= 1) s += __shfl_xor_sync(0xffffffffu, s, o);
    if (lane == 0) g_ada[n*ADA6 + j] = s + ada_b[j];
}

// ---------------- merged weight conversion fp32 -> fp16 ----------------
#define NW0 (3*C_*C_)
#define NW1 (C_*C_)
#define NW2 (HID*C_)
#define NW3 (C_*HID)
#define NWTOT (NW0+NW1+NW2+NW3)
__global__ void f2h_all(const float* __restrict__ s0, const float* __restrict__ s1,
                        const float* __restrict__ s2, const float* __restrict__ s3) {
    int i = (blockIdx.x * blockDim.x + threadIdx.x) * 4;
    const float* s;
    __half* d;
    int off;
    if (i < NW0)                 { s = s0; d = g_wqkv;  off = i; }
    else if (i < NW0+NW1)        { s = s1; d = g_wproj; off = i - NW0; }
    else if (i < NW0+NW1+NW2)    { s = s2; d = g_wfc1;  off = i - NW0 - NW1; }
    else if (i < NWTOT)          { s = s3; d = g_wfc2;  off = i - NW0 - NW1 - NW2; }
    else return;
    float4 v = *(const float4*)(s + off);
    ((__half2*)(d + off))[0] = __floats2half2_rn(v.x, v.y);
    ((__half2*)(d + off))[1] = __floats2half2_rn(v.z, v.w);
}

// ---------------- LayerNorm + adaLN modulation -> fp16 (ln0 only) ----------------
__global__ void __launch_bounds__(192) ln_mod_kernel(const float* __restrict__ xin) {
    const int t = blockIdx.x;
    const int tid = threadIdx.x;
    const int wid = tid >> 5, lane = tid & 31;
    const int win = t >> 6, tw = t & 63;
    const int n = win >> 6;
    const int wi = win & 63;
    const int gi = ((wi >> 3) << 3) + (tw >> 3);
    const int gj = ((wi & 7) << 3) + (tw & 7);
    const int i0 = (gi + 4) & 63, j0 = (gj + 4) & 63;
    const float* xr = xin + (((size_t)n << 12) + (i0 << 6) + j0) * C_;

    const int cix = tid * 4;
    float4 v = *(const float4*)(xr + cix);
    float s  = v.x + v.y + v.z + v.w;
    float ss = v.x*v.x + v.y*v.y + v.z*v.z + v.w*v.w;
    __shared__ float red[14];
    #pragma unroll
    for (int o = 16; o > 0; o >>= 1) {
        s  += __shfl_xor_sync(0xffffffffu, s,  o);
        ss += __shfl_xor_sync(0xffffffffu, ss, o);
    }
    if (lane == 0) { red[wid] = s; red[6 + wid] = ss; }
    __syncthreads();
    if (tid == 0) {
        float a = 0.f, b = 0.f;
        #pragma unroll
        for (int w = 0; w < 6; w++) { a += red[w]; b += red[6 + w]; }
        const float mean = a * (1.f / 768.f);
        const float var  = b * (1.f / 768.f) - mean * mean;
        red[12] = mean;
        red[13] = rsqrtf(var + 1e-6f);
    }
    __syncthreads();
    const float mean = red[12], rstd = red[13];
    const float4 sc = *(const float4*)(g_ada + n*ADA6 + 1 * C_ + cix);
    const float4 sh = *(const float4*)(g_ada + n*ADA6 + 0 * C_ + cix);
    uint2 o;
    o.x = packh((v.x - mean) * rstd * (1.f + sc.x) + sh.x,
                (v.y - mean) * rstd * (1.f + sc.y) + sh.y);
    o.y = packh((v.z - mean) * rstd * (1.f + sc.z) + sh.z,
                (v.w - mean) * rstd * (1.f + sc.w) + sh.w);
    *(uint2*)(g_actA + (size_t)t * C_ + cix) = o;
}

// ---------------- HMMA fp16 GEMM (fp32 acc): C[m,n] = sum_k A[m,k]*W[n,k] ----------------
// CTA 128x256, 8 warps (2x4), warp 64x64. 4-deep ring, reg-double-buffered frags.
// MODE 1 fuses ln_mod<1>: last CTA per bm-block LNs its 128 rows -> g_actC (no alias).
#define BM 128
#define BN 256
#define BUFB ((BM + BN) * 128)
#define GEMM_SMEM (4 * BUFB)

template<int MODE>
__global__ void __launch_bounds__(256, 1) gemm_tc(
    const float* __restrict__ bias,
    const float* __restrict__ x_seq,
    float* __restrict__ dout)
{
    constexpr int K   = (MODE == 3) ? HID : C_;
    constexpr int NCH = K / KC;
    const __half* A = (MODE == 3) ? g_actB : (MODE == 2) ? g_actC : g_actA;
    const __half* W = (MODE == 0) ? g_wqkv : (MODE == 1) ? g_wproj
                    : (MODE == 2) ? g_wfc1 : g_wfc2;

    extern __shared__ char smem[];
    const uint32_t s0 = smem_u32(smem);
    const int tid = threadIdx.x;
    const int wid = tid >> 5, lane = tid & 31;
    const int bm = blockIdx.y * BM, bn = blockIdx.x * BN;

    const __half* Brow = W + (size_t)(bn + tid) * K;
    const __half* Arow = A + (size_t)(bm + (tid & 127)) * K;
    uint32_t bofs[8], aofs[8];
    #pragma unroll
    for (int s = 0; s < 8; s++) {
        bofs[s] = 16384u + swz((uint32_t)tid * 128 + s * 16);
        aofs[s] = swz((uint32_t)(tid & 127) * 128 + s * 16);
    }
    auto load_chunk = [&](int i) {
        const uint32_t buf = s0 + (uint32_t)(i & 3) * BUFB;
        const __half* bsrc = Brow + i * KC;
        #pragma unroll
        for (int s = 0; s < 8; s++) cp16(buf + bofs[s], bsrc + s * 8);
        if (tid < 128) {
            const __half* asrc = Arow + i * KC;
            #pragma unroll
            for (int s = 0; s < 8; s++) cp16(buf + aofs[s], asrc + s * 8);
        }
        cp_commit();
    };
    load_chunk(0); load_chunk(1); load_chunk(2);

    const int wm = wid >> 2, wn = wid & 3;
    uint32_t aOff[4], aXor[4];
    #pragma unroll
    for (int mi = 0; mi < 4; mi++) {
        const int r = wm * 64 + mi * 16 + (lane & 15);
        aOff[mi] = (uint32_t)r * 128 + ((lane >> 4) << 4);
        aXor[mi] = ((uint32_t)(r & 7)) << 4;
    }
    uint32_t bOff[4], bXor[4];
    #pragma unroll
    for (int nj = 0; nj < 4; nj++) {
        const int r = wn * 64 + nj * 16 + (lane & 15);
        bOff[nj] = 16384u + (uint32_t)r * 128 + ((lane >> 4) << 4);
        bXor[nj] = ((uint32_t)(r & 7)) << 4;
    }

    uint32_t aR[2][4][4], bR[2][4][4];
    auto do_ldsm = [&](uint32_t buf, int ks, int p) {
        const uint32_t kb = (uint32_t)ks * 32;
        #pragma unroll
        for (int mi = 0; mi < 4; mi++)
            ldsm4(aR[p][mi][0], aR[p][mi][1], aR[p][mi][2], aR[p][mi][3],
                  buf + (aOff[mi] & ~0x70u) + (((aOff[mi] & 0x70u) + kb) ^ aXor[mi]));
        #pragma unroll
        for (int nj = 0; nj < 4; nj++)
            ldsm4(bR[p][nj][0], bR[p][nj][1], bR[p][nj][2], bR[p][nj][3],
                  buf + (bOff[nj] & ~0x70u) + (((bOff[nj] & 0x70u) + kb) ^ bXor[nj]));
    };

    float acc[4][8][4];
    #pragma unroll
    for (int mi = 0; mi < 4; mi++)
        #pragma unroll
        for (int ni = 0; ni < 8; ni++)
            #pragma unroll
            for (int e = 0; e < 4; e++) acc[mi][ni][e] = 0.f;

    cp_wait<2>();
    __syncthreads();
    do_ldsm(s0, 0, 0);

    for (int i = 0; i < NCH; i++) {
        const uint32_t buf = s0 + (uint32_t)(i & 3) * BUFB;
        #pragma unroll
        for (int ks = 0; ks < 4; ks++) {
            const int p = ks & 1;
            if (ks < 3) {
                do_ldsm(buf, ks + 1, p ^ 1);
            } else if (i + 1 < NCH) {
                if (i + 2 < NCH) cp_wait<1>(); else cp_wait<0>();
                __syncthreads();
                if (i + 3 < NCH) load_chunk(i + 3);
                do_ldsm(s0 + (uint32_t)((i + 1) & 3) * BUFB, 0, p ^ 1);
            }
            #pragma unroll
            for (int mi = 0; mi < 4; mi++) {
                #pragma unroll
                for (int nj = 0; nj < 4; nj++) {
                    mma_hf(acc[mi][nj*2+0], aR[p][mi], bR[p][nj][0], bR[p][nj][2]);
                    mma_hf(acc[mi][nj*2+1], aR[p][mi], bR[p][nj][1], bR[p][nj][3]);
                }
            }
        }
    }

    // ---------------- epilogue ----------------
    const int rIn = lane >> 2;
    const int cIn = (lane & 3) * 2;
    #pragma unroll
    for (int mi = 0; mi < 4; mi++) {
        #pragma unroll
        for (int h = 0; h < 2; h++) {
            const int row = bm + wm * 64 + mi * 16 + rIn + h * 8;
            if constexpr (MODE == 0) {
                const int win = row >> 6, tw = row & 63;
                #pragma unroll
                for (int ni = 0; ni < 8; ni++) {
                    const int g = bn + wn * 64 + ni * 8 + cIn;
                    const int which = g / 768;
                    const int head = (g >> 6) % 12;
                    const int d0 = g & 63;
                    __half* dst = g_qkv + (size_t)which * REGSZ
                               + (((size_t)(win * NHEAD + head)) << 12) + (tw << 6) + d0;
                    *(__half2*)dst = __floats2half2_rn(
                        acc[mi][ni][h*2+0] + __ldg(bias + g),
                        acc[mi][ni][h*2+1] + __ldg(bias + g + 1));
                }
            } else if constexpr (MODE == 1) {
                const int win = row >> 6, tw = row & 63;
                const int n = win >> 6, wi = win & 63;
                const int gi = ((wi >> 3) << 3) + (tw >> 3);
                const int gj = ((wi & 7) << 3) + (tw & 7);
                const int i0 = (gi + 4) & 63, j0 = (gj + 4) & 63;
                const size_t srow = ((size_t)n << 12) + (i0 << 6) + j0;
                const float* xr = x_seq + srow * C_;
                float* dst = g_xnew + srow * C_;
                const float* gp = g_ada + n * ADA6 + 2 * C_;
                #pragma unroll
                for (int ni = 0; ni < 8; ni++) {
                    const int g = bn + wn * 64 + ni * 8 + cIn;
                    float2 v;
                    v.x = xr[g]   + gp[g]   * (acc[mi][ni][h*2+0] + __ldg(bias + g));
                    v.y = xr[g+1] + gp[g+1] * (acc[mi][ni][h*2+1] + __ldg(bias + g + 1));
                    *(float2*)(dst + g) = v;
                }
            } else if constexpr (MODE == 2) {
                __half* dst = g_actB + (size_t)row * HID;
                #pragma unroll
                for (int ni = 0; ni < 8; ni++) {
                    const int g = bn + wn * 64 + ni * 8 + cIn;
                    float u0 = acc[mi][ni][h*2+0] + __ldg(bias + g);
                    float u1 = acc[mi][ni][h*2+1] + __ldg(bias + g + 1);
                    float t0 = tanha(0.7978845608028654f * (u0 + 0.044715f * u0 * u0 * u0));
                    float t1 = tanha(0.7978845608028654f * (u1 + 0.044715f * u1 * u1 * u1));
                    *(__half2*)(dst + g) =
                        __floats2half2_rn(0.5f * u0 * (1.f + t0), 0.5f * u1 * (1.f + t1));
                }
            } else {
                const int n = row >> 12;
                const float* xr = g_xnew + (size_t)row * C_;
                const float* gp = g_ada + n * ADA6 + 5 * C_;
                float* dst = dout + (size_t)row * C_;
                #pragma unroll
                for (int ni = 0; ni < 8; ni++) {
                    const int g = bn + wn * 64 + ni * 8 + cIn;
                    float2 v;
                    v.x = xr[g]   + gp[g]   * (acc[mi][ni][h*2+0] + __ldg(bias + g));
                    v.y = xr[g+1] + gp[g+1] * (acc[mi][ni][h*2+1] + __ldg(bias + g + 1));
                    *(float2*)(dst + g) = v;
                }
            }
        }
    }

    // ---------------- MODE 1: fused ln_mod<1> -> g_actC (last CTA per bm-block) ----------------
    if constexpr (MODE == 1) {
        __shared__ int s_old;
        __threadfence();
        __syncthreads();
        if (tid == 0) s_old = atomicAdd(&g_cnt1[blockIdx.y], 1);
        __syncthreads();
        if (s_old == 2) {
            __threadfence();
            for (int r = wid; r < BM; r += 8) {
                const int row = bm + r;
                const int win = row >> 6, tw = row & 63;
                const int n = win >> 6, wi = win & 63;
                const int gi = ((wi >> 3) << 3) + (tw >> 3);
                const int gj = ((wi & 7) << 3) + (tw & 7);
                const int i0 = (gi + 4) & 63, j0 = (gj + 4) & 63;
                const size_t srow = ((size_t)n << 12) + (i0 << 6) + j0;
                const float* xr = g_xnew + srow * C_;
                float4 v[6];
                float s = 0.f, ssq = 0.f;
                #pragma unroll
                for (int q = 0; q < 6; q++) {
                    v[q] = *(const float4*)(xr + q * 128 + lane * 4);
                    s   += v[q].x + v[q].y + v[q].z + v[q].w;
                    ssq += v[q].x*v[q].x + v[q].y*v[q].y + v[q].z*v[q].z + v[q].w*v[q].w;
                }
                #pragma unroll
                for (int o = 16; o > 0; o >>= 1) {
                    s   += __shfl_xor_sync(0xffffffffu, s,   o);
                    ssq += __shfl_xor_sync(0xffffffffu, ssq, o);
                }
                const float mean = s * (1.f / 768.f);
                const float var  = ssq * (1.f / 768.f) - mean * mean;
                const float rstd = rsqrtf(var + 1e-6f);
                const float* scp = g_ada + n * ADA6 + 4 * C_;
                const float* shp = g_ada + n * ADA6 + 3 * C_;
                __half* outr = g_actC + srow * C_;
                #pragma unroll
                for (int q = 0; q < 6; q++) {
                    const int cix = q * 128 + lane * 4;
                    const float4 sc = *(const float4*)(scp + cix);
                    const float4 sh = *(const float4*)(shp + cix);
                    uint2 o;
                    o.x = packh((v[q].x - mean) * rstd * (1.f + sc.x) + sh.x,
                                (v[q].y - mean) * rstd * (1.f + sc.y) + sh.y);
                    o.y = packh((v[q].z - mean) * rstd * (1.f + sc.z) + sh.z,
                                (v[q].w - mean) * rstd * (1.f + sc.w) + sh.w);
                    *(uint2*)(outr + cix) = o;
                }
            }
            __syncthreads();
            if (tid == 0) g_cnt1[blockIdx.y] = 0;   // reset for next graph replay
        }
    }
}

// ---------------- HMMA window attention: 2 heads per CTA, fp16 in, fp32 acc ----------------
__global__ void __launch_bounds__(256, 4) attn_hmma() {
    __shared__ __align__(1024) __half sm[2 * 3 * 4096];
    const uint32_t sb = smem_u32(sm);
    const int bid = blockIdx.x;
    const int win = bid / 6, hp = bid - 6 * win;
    const int tid = threadIdx.x, wid = tid >> 5, lane = tid & 31;

    {
        const int hh = tid >> 7;
        const int t0 = tid & 127;
        const __half* qb = g_qkv + (size_t)(win * NHEAD + hp * 2 + hh) * 4096;
        const uint32_t hsb = sb + (uint32_t)hh * 24576u;
        const int r = t0 & 63;
        const __half* src = ((t0 < 64) ? qb : (qb + REGSZ)) + r * 64;
        const uint32_t base = hsb + ((t0 < 64) ? 0u : 8192u);
        #pragma unroll
        for (int s = 0; s < 8; s++)
            cp16(base + swz((uint32_t)r * 128 + s * 16), src + s * 8);
        const __half* vb = qb + 2 * REGSZ;
        const int vr = t0 >> 1;
        const int c0 = (t0 & 1) * 4;
        #pragma unroll
        for (int s = 0; s < 4; s++)
            cp16(hsb + 16384u + swz((uint32_t)vr * 128 + (c0 + s) * 16),
                 vb + vr * 64 + (c0 + s) * 8);
    }
    cp_commit();
    cp_wait<0>();
    __syncthreads();

    const int hw = wid >> 2, w4 = wid & 3;
    const uint32_t hsb = sb + (uint32_t)hw * 24576u;
    const int head = hp * 2 + hw;
    const int lr = lane & 15, lc = lane >> 4;

    uint32_t aF[4][4];
    #pragma unroll
    for (int ks = 0; ks < 4; ks++)
        ldsm4(aF[ks][0], aF[ks][1], aF[ks][2], aF[ks][3],
              hsb + swz((uint32_t)(16 * w4 + lr) * 128 + lc * 16 + ks * 32));

    float S[8][4];
    #pragma unroll
    for (int f = 0; f < 8; f++)
        #pragma unroll
        for (int e = 0; e < 4; e++) S[f][e] = 0.f;

    #pragma unroll
    for (int nj = 0; nj < 4; nj++) {
        #pragma unroll
        for (int ks = 0; ks < 4; ks++) {
            uint32_t b0, b1, b2, b3;
            ldsm4(b0, b1, b2, b3,
                  hsb + 8192u + swz((uint32_t)(nj * 16 + lr) * 128 + lc * 16 + ks * 32));
            mma_hf(S[2*nj+0], aF[ks], b0, b2);
            mma_hf(S[2*nj+1], aF[ks], b1, b3);
        }
    }

    float mx0 = -1e30f, mx1 = -1e30f;
    #pragma unroll
    for (int f = 0; f < 8; f++) {
        #pragma unroll
        for (int e = 0; e < 4; e++) S[f][e] *= 0.125f;
        mx0 = fmaxf(mx0, fmaxf(S[f][0], S[f][1]));
        mx1 = fmaxf(mx1, fmaxf(S[f][2], S[f][3]));
    }
    mx0 = fmaxf(mx0, __shfl_xor_sync(0xffffffffu, mx0, 1));
    mx0 = fmaxf(mx0, __shfl_xor_sync(0xffffffffu, mx0, 2));
    mx1 = fmaxf(mx1, __shfl_xor_sync(0xffffffffu, mx1, 1));
    mx1 = fmaxf(mx1, __shfl_xor_sync(0xffffffffu, mx1, 2));
    float sm0 = 0.f, sm1 = 0.f;
    #pragma unroll
    for (int f = 0; f < 8; f++) {
        S[f][0] = __expf(S[f][0] - mx0); sm0 += S[f][0];
        S[f][1] = __expf(S[f][1] - mx0); sm0 += S[f][1];
        S[f][2] = __expf(S[f][2] - mx1); sm1 += S[f][2];
        S[f][3] = __expf(S[f][3] - mx1); sm1 += S[f][3];
    }
    sm0 += __shfl_xor_sync(0xffffffffu, sm0, 1);
    sm0 += __shfl_xor_sync(0xffffffffu, sm0, 2);
    sm1 += __shfl_xor_sync(0xffffffffu, sm1, 1);
    sm1 += __shfl_xor_sync(0xffffffffu, sm1, 2);
    const float iv0 = 1.f / sm0, iv1 = 1.f / sm1;
    #pragma unroll
    for (int f = 0; f < 8; f++) {
        S[f][0] *= iv0; S[f][1] *= iv0; S[f][2] *= iv1; S[f][3] *= iv1;
    }

    uint32_t aP[4][4];
    #pragma unroll
    for (int ks = 0; ks < 4; ks++) {
        aP[ks][0] = packh(S[2*ks+0][0], S[2*ks+0][1]);
        aP[ks][1] = packh(S[2*ks+0][2], S[2*ks+0][3]);
        aP[ks][2] = packh(S[2*ks+1][0], S[2*ks+1][1]);
        aP[ks][3] = packh(S[2*ks+1][2], S[2*ks+1][3]);
    }

    float O[8][4];
    #pragma unroll
    for (int f = 0; f < 8; f++)
        #pragma unroll
        for (int e = 0; e < 4; e++) O[f][e] = 0.f;
    #pragma unroll
    for (int ks = 0; ks < 4; ks++) {
        #pragma unroll
        for (int nj = 0; nj < 4; nj++) {
            uint32_t r0, r1, r2, r3;
            ldsm4t(r0, r1, r2, r3,
                   hsb + 16384u + swz((uint32_t)(16 * ks + lr) * 128 + (2 * nj + lc) * 16));
            mma_hf(O[2*nj+0], aP[ks], r0, r1);
            mma_hf(O[2*nj+1], aP[ks], r2, r3);
        }
    }

    const int r0row = 16 * w4 + (lane >> 2);
    const int q2 = (lane & 3) * 2;
    #pragma unroll
    for (int f = 0; f < 8; f++) {
        __half* d0 = g_actA + (size_t)(win * 64 + r0row) * C_ + head * 64 + 8 * f + q2;
        *(__half2*)d0 = __floats2half2_rn(O[f][0], O[f][1]);
        *(__half2*)(d0 + 8 * C_) = __floats2half2_rn(O[f][2], O[f][3]);
    }
}

// ---------------- launcher ----------------
extern "C" void kernel_launch(void* const* d_in, const int* in_sizes, int n_in,
                              void* d_out, int out_size) {
    const float* x_seq  = (const float*)d_in[0];
    const float* c_in   = (const float*)d_in[1];
    const float* qkv_w  = (const float*)d_in[2];
    const float* qkv_b  = (const float*)d_in[3];
    const float* proj_w = (const float*)d_in[4];
    const float* proj_b = (const float*)d_in[5];
    const float* fc1_w  = (const float*)d_in[6];
    const float* fc1_b  = (const float*)d_in[7];
    const float* fc2_w  = (const float*)d_in[8];
    const float* fc2_b  = (const float*)d_in[9];
    const float* ada_w  = (const float*)d_in[10];
    const float* ada_b  = (const float*)d_in[11];
    float* out = (float*)d_out;

    cudaFuncSetAttribute(gemm_tc<0>, cudaFuncAttributeMaxDynamicSharedMemorySize, GEMM_SMEM);
    cudaFuncSetAttribute(gemm_tc<1>, cudaFuncAttributeMaxDynamicSharedMemorySize, GEMM_SMEM);
    cudaFuncSetAttribute(gemm_tc<2>, cudaFuncAttributeMaxDynamicSharedMemorySize, GEMM_SMEM);
    cudaFuncSetAttribute(gemm_tc<3>, cudaFuncAttributeMaxDynamicSharedMemorySize, GEMM_SMEM);

    ada_kernel<<<dim3(ADA6/4, NB), 128>>>(c_in, ada_w, ada_b);              // 1
    f2h_all<<<(NWTOT/4 + 255)/256, 256>>>(qkv_w, proj_w, fc1_w, fc2_w);     // 2
    ln_mod_kernel<<<M_TOT, 192>>>(x_seq);                                   // 3
    gemm_tc<0><<<dim3(9, 256), 256, GEMM_SMEM>>>(qkv_b, nullptr, nullptr);  // 4 <- ncu
    attn_hmma<<<512*6, 256>>>();                                            // 5
    gemm_tc<1><<<dim3(3, 256), 256, GEMM_SMEM>>>(proj_b, x_seq, nullptr);   // 6 (fused ln1 -> g_actC)
    gemm_tc<2><<<dim3(12, 256), 256, GEMM_SMEM>>>(fc1_b, nullptr, nullptr); // 7 (reads g_actC)
    gemm_tc<3><<<dim3(3, 256), 256, GEMM_SMEM>>>(fc2_b, nullptr, out);      // 8
}